// round 16
// baseline (speedup 1.0000x reference)
#include <cuda_runtime.h>
#include <cuda_bf16.h>
#include <cuda_fp16.h>
#include <math.h>
#include <stdint.h>

#define Bsz 2
#define Nn  1024
#define Dd  512
#define Hh  16
#define DHd 32

// Scratch (device globals; no allocation allowed)
__device__ float g_y[Bsz*Nn*Dd];         // pre-LN residual

// fp16 operands
__device__ __half g_xhi[Bsz*Nn*Dd],  g_xlo[Bsz*Nn*Dd];   // x hi/lo
__device__ __half g_w16[1536*Dd];                         // att_w single
__device__ __half g_fw16[Dd*Dd];                          // ff_w single
__device__ __half g_atthi[Bsz*Nn*Dd], g_attlo[Bsz*Nn*Dd]; // attn out hi/lo
// Attention operands: Q hi/lo (pre-scaled), K single, V single
__device__ __half g_qh16[Bsz*Hh*Nn*DHd], g_ql16[Bsz*Hh*Nn*DHd];
__device__ __half g_k16 [Bsz*Hh*Nn*DHd];
__device__ __half g_v16 [Bsz*Hh*Nn*DHd];
// fused additive bias, fp16, [B,H,N,N] (masked entries = -60000)
__device__ __half g_bias[(size_t)Bsz*Hh*Nn*Nn];
// split-K partials: [B*4 splits][H][N][32] fp32 + row sums
__device__ float g_po[(size_t)Bsz*4*Hh*Nn*DHd];
__device__ float g_pl[(size_t)Bsz*4*Hh*Nn];

// ===================== warp-MMA helpers ====================================
__device__ __forceinline__ uint32_t smem_u32(const void* p) {
    uint32_t a;
    asm("{ .reg .u64 t; cvta.to.shared.u64 t, %1; cvt.u32.u64 %0, t; }"
        : "=r"(a) : "l"(p));
    return a;
}
__device__ __forceinline__ void ldsm_x4(uint32_t* r, uint32_t addr) {
    asm volatile("ldmatrix.sync.aligned.m8n8.x4.shared.b16 {%0,%1,%2,%3}, [%4];"
        : "=r"(r[0]), "=r"(r[1]), "=r"(r[2]), "=r"(r[3]) : "r"(addr));
}
__device__ __forceinline__ void ldsm_x4_t(uint32_t* r, uint32_t addr) {
    asm volatile("ldmatrix.sync.aligned.m8n8.x4.trans.shared.b16 {%0,%1,%2,%3}, [%4];"
        : "=r"(r[0]), "=r"(r[1]), "=r"(r[2]), "=r"(r[3]) : "r"(addr));
}
__device__ __forceinline__ void mma_16816h(float* c, const uint32_t* a, const uint32_t* b) {
    asm volatile("mma.sync.aligned.m16n8k16.row.col.f32.f16.f16.f32 "
        "{%0,%1,%2,%3}, {%4,%5,%6,%7}, {%8,%9}, {%0,%1,%2,%3};"
        : "+f"(c[0]), "+f"(c[1]), "+f"(c[2]), "+f"(c[3])
        : "r"(a[0]), "r"(a[1]), "r"(a[2]), "r"(a[3]), "r"(b[0]), "r"(b[1]));
}
__device__ __forceinline__ void cp_async16(uint32_t saddr, const void* gaddr) {
    asm volatile("cp.async.cg.shared.global [%0], [%1], 16;"
                 :: "r"(saddr), "l"(gaddr) : "memory");
}
__device__ __forceinline__ uint32_t hpack2(float x0, float x1) {
    __half2 h = __floats2half2_rn(x0, x1);
    return *(uint32_t*)&h;
}
__device__ __forceinline__ void splith2(float x0, float x1, uint32_t& uh, uint32_t& ul) {
    __half h0 = __float2half_rn(x0), h1 = __float2half_rn(x1);
    __half l0 = __float2half_rn(x0 - __half2float(h0));
    __half l1 = __float2half_rn(x1 - __half2float(h1));
    uh = (uint32_t)__half_as_ushort(h0) | ((uint32_t)__half_as_ushort(h1) << 16);
    ul = (uint32_t)__half_as_ushort(l0) | ((uint32_t)__half_as_ushort(l1) << 16);
}

// ---------------------------------------------------------------------------
// Kernel 0: preprocessing — x -> fp16 hi/lo; att_w, ff_w -> fp16 single.
// ---------------------------------------------------------------------------
#define SPLIT_N1 (Bsz*Nn*Dd/4)
#define SPLIT_N2 (1536*Dd/4)
#define SPLIT_N3 (Dd*Dd/4)
#define SPLIT_TOT (SPLIT_N1 + SPLIT_N2 + SPLIT_N3)

__global__ __launch_bounds__(256) void split_all(
    const float* __restrict__ x, const float* __restrict__ w,
    const float* __restrict__ fw,
    __half* __restrict__ xhi, __half* __restrict__ xlo,
    __half* __restrict__ w16, __half* __restrict__ fw16)
{
    int idx = blockIdx.x * 256 + threadIdx.x;
    if (idx < SPLIT_N1) {
        float4 v = ((const float4*)x)[idx];
        uint2 uh, ul;
        splith2(v.x, v.y, uh.x, ul.x);
        splith2(v.z, v.w, uh.y, ul.y);
        *(uint2*)&xhi[(size_t)idx*4] = uh;
        *(uint2*)&xlo[(size_t)idx*4] = ul;
    } else if (idx < SPLIT_N1 + SPLIT_N2) {
        int i = idx - SPLIT_N1;
        float4 v = ((const float4*)w)[i];
        uint2 pk;
        pk.x = hpack2(v.x, v.y);
        pk.y = hpack2(v.z, v.w);
        *(uint2*)&w16[(size_t)i*4] = pk;
    } else if (idx < SPLIT_TOT) {
        int i = idx - SPLIT_N1 - SPLIT_N2;
        float4 v = ((const float4*)fw)[i];
        uint2 pk;
        pk.x = hpack2(v.x, v.y);
        pk.y = hpack2(v.z, v.w);
        *(uint2*)&fw16[(size_t)i*4] = pk;
    }
}

// ---------------------------------------------------------------------------
// Kernel 0b: fused bias precompute (fp16; masked -> -60000).
// ---------------------------------------------------------------------------
__global__ __launch_bounds__(256) void bias_kernel(
    const float* __restrict__ pdist, const float* __restrict__ angle,
    const float* __restrict__ adj,   const unsigned char* __restrict__ mask,
    const float* __restrict__ gamma_p, const float* __restrict__ gamma_adj,
    const float* __restrict__ w_bias)
{
    const int idx = blockIdx.x * 256 + threadIdx.x;
    const int jc = idx & 255;
    const int bi = idx >> 8;
    const int b = bi >> 10;
    const int ii = bi & 1023;
    const int j = jc * 4;
    const size_t base = (size_t)bi * Nn + j;

    const float4 pd  = *(const float4*)&pdist[base];
    const float4 aj  = *(const float4*)&adj[base];
    const float4 an0 = *(const float4*)&angle[2*base];
    const float4 an1 = *(const float4*)&angle[2*base + 4];
    const unsigned char* mk = mask + b*Nn + j;
    const bool m0 = mk[0], m1 = mk[1], m2 = mk[2], m3 = mk[3];

    #pragma unroll
    for (int h = 0; h < Hh; h++) {
        const float gp = gamma_p[h], ga = gamma_adj[h];
        const float w0 = w_bias[2*h], w1 = w_bias[2*h+1];
        float s0 = -gp*pd.x + w0*an0.x + w1*an0.y + ga*aj.x;
        float s1 = -gp*pd.y + w0*an0.z + w1*an0.w + ga*aj.y;
        float s2 = -gp*pd.z + w0*an1.x + w1*an1.y + ga*aj.z;
        float s3 = -gp*pd.w + w0*an1.z + w1*an1.w + ga*aj.w;
        if (m0) s0 = -60000.f;
        if (m1) s1 = -60000.f;
        if (m2) s2 = -60000.f;
        if (m3) s3 = -60000.f;
        uint2 pk;
        pk.x = hpack2(s0, s1);
        pk.y = hpack2(s2, s3);
        const size_t off = (((size_t)(b*Hh + h)*Nn + ii)*Nn + j);
        *(uint2*)&g_bias[off] = pk;
    }
}

// ---------------------------------------------------------------------------
// cp.async double-buffered fp16 MMA mainloop (proven R13/R14).
// ---------------------------------------------------------------------------
template<int MFR>
__device__ __forceinline__ void mma_mainloop(
    const __half* __restrict__ gAhi, const __half* __restrict__ gAlo,
    const __half* __restrict__ gB,
    int m0, int o0, char* smem, float (&acc)[MFR][4][4])
{
    constexpr int MT = MFR * 32;
    constexpr int S_ALO = MT * 64;
    constexpr int S_B   = 2 * MT * 64;
    constexpr int STAGE = 2 * MT * 64 + 8192;
    const int tid = threadIdx.x;
    const int warp = tid >> 5, lane = tid & 31;
    const int wm = warp >> 2, wn = warp & 3;
    const uint32_t sb = smem_u32(smem);

    #define ISSUE_CHUNK(kc, st) do { \
        uint32_t s0 = sb + (st) * STAGE; \
        _Pragma("unroll") \
        for (int i = 0; i < MFR/2; i++) { \
            int u = tid + i*256; \
            int row = u >> 2, q = u & 3; \
            uint32_t off = row*64 + ((uint32_t)(q ^ ((row>>1)&3)) << 4); \
            size_t g = (size_t)(m0 + row)*512 + (kc)*32 + q*8; \
            cp_async16(s0 + off,         &gAhi[g]); \
            cp_async16(s0 + S_ALO + off, &gAlo[g]); \
        } \
        _Pragma("unroll") \
        for (int i = 0; i < 2; i++) { \
            int u = tid + i*256; \
            int row = u >> 2, q = u & 3; \
            uint32_t off = row*64 + ((uint32_t)(q ^ ((row>>1)&3)) << 4); \
            size_t g = (size_t)(o0 + row)*512 + (kc)*32 + q*8; \
            cp_async16(s0 + S_B + off, &gB[g]); \
        } \
        asm volatile("cp.async.commit_group;" ::: "memory"); \
    } while (0)

    ISSUE_CHUNK(0, 0);
    ISSUE_CHUNK(1, 1);

    for (int kc = 0; kc < 16; kc++) {
        if (kc < 15) asm volatile("cp.async.wait_group 1;" ::: "memory");
        else         asm volatile("cp.async.wait_group 0;" ::: "memory");
        __syncthreads();
        const uint32_t s0 = sb + (uint32_t)(kc & 1) * STAGE;
        #pragma unroll
        for (int ks = 0; ks < 2; ks++) {
            uint32_t bh[4][2];
            #pragma unroll
            for (int p = 0; p < 2; p++) {
                int nrow = wn*32 + p*16 + (lane & 7) + ((lane >> 4) << 3);
                int qb = ks*2 + ((lane >> 3) & 1);
                uint32_t off = nrow*64 + ((uint32_t)(qb ^ ((nrow>>1)&3)) << 4);
                uint32_t r[4];
                ldsm_x4(r, s0 + S_B + off);
                bh[2*p][0] = r[0]; bh[2*p][1] = r[1];
                bh[2*p+1][0] = r[2]; bh[2*p+1][1] = r[3];
            }
            #pragma unroll
            for (int mf = 0; mf < MFR; mf++) {
                int arow = wm*(MFR*16) + mf*16 + (lane & 15);
                int qb = ks*2 + (lane >> 4);
                uint32_t off = arow*64 + ((uint32_t)(qb ^ ((arow>>1)&3)) << 4);
                uint32_t ah[4], al[4];
                ldsm_x4(ah, s0 + off);
                ldsm_x4(al, s0 + S_ALO + off);
                #pragma unroll
                for (int nf = 0; nf < 4; nf++) {
                    mma_16816h(acc[mf][nf], ah, bh[nf]);
                    mma_16816h(acc[mf][nf], al, bh[nf]);
                }
            }
        }
        __syncthreads();
        if (kc + 2 < 16) ISSUE_CHUNK(kc + 2, kc & 1);
    }
    #undef ISSUE_CHUNK
}

#define GEMM_SMEM (2 * (2*64*64 + 8192))   // MFR=2: 32768 bytes (2 stages)

// ---------------------------------------------------------------------------
// Kernel 1: QKV GEMM. CTA 64x128, grid (12, 32). Epilogue writes fp16:
// Q hi/lo (pre-scaled), K single, V single, all [B,H,N,32].
// ---------------------------------------------------------------------------
__global__ __launch_bounds__(256) void gemm_qkv_mma()
{
    extern __shared__ __align__(16) char smem[];
    const int m0 = blockIdx.y * 64, o0 = blockIdx.x * 128;
    float acc[2][4][4] = {};
    mma_mainloop<2>(g_xhi, g_xlo, g_w16, m0, o0, smem, acc);

    const float SCALE = 0.17677669529663689f;  // 1/sqrt(32)
    const int tid = threadIdx.x, warp = tid >> 5, lane = tid & 31;
    const int wm = warp >> 2, wn = warp & 3;
    const int bb = m0 >> 10;
    #pragma unroll
    for (int mf = 0; mf < 2; mf++) {
        int r0 = (m0 & 1023) + wm*32 + mf*16 + (lane >> 2);
        #pragma unroll
        for (int nf = 0; nf < 4; nf++) {
            int o = o0 + wn*32 + nf*8 + (lane & 3)*2;
            int which = o >> 9, h = (o >> 5) & 15, d = o & 31;
            size_t e0 = ((size_t)(bb*Hh + h)*Nn + r0)*DHd + d;
            size_t e1 = e0 + 8*DHd;
            if (which == 0) {
                uint32_t uh, ul;
                splith2(acc[mf][nf][0]*SCALE, acc[mf][nf][1]*SCALE, uh, ul);
                *(uint32_t*)&g_qh16[e0] = uh; *(uint32_t*)&g_ql16[e0] = ul;
                splith2(acc[mf][nf][2]*SCALE, acc[mf][nf][3]*SCALE, uh, ul);
                *(uint32_t*)&g_qh16[e1] = uh; *(uint32_t*)&g_ql16[e1] = ul;
            } else if (which == 1) {
                *(uint32_t*)&g_k16[e0] = hpack2(acc[mf][nf][0], acc[mf][nf][1]);
                *(uint32_t*)&g_k16[e1] = hpack2(acc[mf][nf][2], acc[mf][nf][3]);
            } else {
                *(uint32_t*)&g_v16[e0] = hpack2(acc[mf][nf][0], acc[mf][nf][1]);
                *(uint32_t*)&g_v16[e1] = hpack2(acc[mf][nf][2], acc[mf][nf][3]);
            }
        }
    }
}

// ---------------------------------------------------------------------------
// Kernel 2: Split-K tensor-core attention, K split in 4 quarters of 4 tiles.
// Exact decomposition (no online max): partial o, partial l; combine adds.
// Grid (16 qtiles, 16 heads, B*4). Block 128 thr (4 warps x 16 queries).
// Per stage SMEM: K(4096) | V(4096) | bias(9216, 144B rows, conflict-free).
// ---------------------------------------------------------------------------
#define ASTAGE 17408   // 4096 + 4096 + 9216

__global__ __launch_bounds__(128) void attn_mma(const __half* __restrict__ gbias)
{
    __shared__ __align__(16) char sQh[4096];
    __shared__ __align__(16) char sQl[4096];
    __shared__ __align__(16) char sKV[2][ASTAGE];

    const int s = blockIdx.z;            // b*4 + split
    const int b = s >> 2, split = s & 3;
    const int h = blockIdx.y;
    const int i0 = blockIdx.x * 64;
    const int t = threadIdx.x, w = t >> 5, lane = t & 31;
    const int jbase = split * 4;         // first key tile of this split

    const size_t ho = (size_t)(b*Hh + h)*Nn*DHd;
    const __half* gQh = g_qh16 + ho;
    const __half* gQl = g_ql16 + ho;
    const __half* gK  = g_k16  + ho;
    const __half* gV  = g_v16  + ho;
    const __half* gB  = gbias + ((size_t)(b*Hh + h)*Nn + i0)*Nn;  // [64][N]

    const uint32_t sbQh = smem_u32(sQh), sbQl = smem_u32(sQl);
    const uint32_t sbKV = smem_u32(sKV);

    #define ATTN_ISSUE(jt, st) do { \
        const int _j0 = (jt)*64; \
        uint32_t s0 = sbKV + (uint32_t)(st)*ASTAGE; \
        _Pragma("unroll") \
        for (int u0 = 0; u0 < 2; u0++) { \
            int u = t + u0*128; \
            int row = u >> 2, q = u & 3; \
            uint32_t off = row*64 + ((uint32_t)(q ^ ((row>>1)&3)) << 4); \
            size_t g = (size_t)(_j0 + row)*DHd + q*8; \
            cp_async16(s0 + off,        &gK[g]); \
            cp_async16(s0 + 4096 + off, &gV[g]); \
        } \
        _Pragma("unroll") \
        for (int u0 = 0; u0 < 4; u0++) { \
            int u = t + u0*128; \
            int row = u >> 3, q = u & 7; \
            cp_async16(s0 + 8192 + row*144 + q*16, \
                       &gB[(size_t)row*Nn + _j0 + q*8]); \
        } \
        asm volatile("cp.async.commit_group;" ::: "memory"); \
    } while (0)

    // Stage Q tile; kick off first two K/V/bias tiles of this split
    #pragma unroll
    for (int u0 = 0; u0 < 2; u0++) {
        int u = t + u0*128;
        int row = u >> 2, q = u & 3;
        uint32_t off = row*64 + ((uint32_t)(q ^ ((row>>1)&3)) << 4);
        size_t g = (size_t)(i0 + row)*DHd + q*8;
        *(uint4*)(sQh + off) = *(const uint4*)&gQh[g];
        *(uint4*)(sQl + off) = *(const uint4*)&gQl[g];
    }
    ATTN_ISSUE(jbase + 0, 0);
    ATTN_ISSUE(jbase + 1, 1);
    __syncthreads();

    uint32_t qh[2][4], ql[2][4];
    #pragma unroll
    for (int ks = 0; ks < 2; ks++) {
        int arow = w*16 + (lane & 15);
        int qb = ks*2 + (lane >> 4);
        uint32_t off = arow*64 + ((uint32_t)(qb ^ ((arow>>1)&3)) << 4);
        ldsm_x4(qh[ks], sbQh + off);
        ldsm_x4(ql[ks], sbQl + off);
    }

    const int qrow = w*16 + (lane >> 2);
    const uint32_t brow0 = 8192 + qrow*144;
    const uint32_t brow1 = 8192 + (qrow + 8)*144;

    float o[4][4] = {};
    float l0 = 0.f, l1 = 0.f;

    for (int jt4 = 0; jt4 < 4; jt4++) {
        if (jt4 < 3) asm volatile("cp.async.wait_group 1;" ::: "memory");
        else         asm volatile("cp.async.wait_group 0;" ::: "memory");
        __syncthreads();
        const uint32_t s0 = sbKV + (uint32_t)(jt4 & 1)*ASTAGE;
        const char* sbias = (const char*)sKV[jt4 & 1];

        #pragma unroll
        for (int kc = 0; kc < 4; kc++) {
            // ---- K fragments (single fp16) ----
            uint32_t kk[2][2][2];
            #pragma unroll
            for (int ks = 0; ks < 2; ks++) {
                int nrow = kc*16 + (lane & 7) + ((lane >> 4) << 3);
                int qb = ks*2 + ((lane >> 3) & 1);
                uint32_t off = nrow*64 + ((uint32_t)(qb ^ ((nrow>>1)&3)) << 4);
                uint32_t r[4];
                ldsm_x4(r, s0 + off);
                kk[ks][0][0] = r[0]; kk[ks][0][1] = r[1];
                kk[ks][1][0] = r[2]; kk[ks][1][1] = r[3];
            }
            // ---- QK^T: (Qhi + Qlo) x K ----
            float c[2][4] = {};
            #pragma unroll
            for (int nt2 = 0; nt2 < 2; nt2++)
                #pragma unroll
                for (int ks = 0; ks < 2; ks++) {
                    mma_16816h(c[nt2], qh[ks], kk[ks][nt2]);
                    mma_16816h(c[nt2], ql[ks], kk[ks][nt2]);
                }
            // ---- bias from SMEM + exp, pack P as fp16 ----
            uint32_t a[4];
            #pragma unroll
            for (int nt2 = 0; nt2 < 2; nt2++) {
                int jb = ((kc*2 + nt2)*8 + (lane & 3)*2) * 2;
                float2 f0 = __half22float2(*(const __half2*)(sbias + brow0 + jb));
                float2 f1 = __half22float2(*(const __half2*)(sbias + brow1 + jb));
                float e0 = __expf(c[nt2][0] + f0.x);
                float e1 = __expf(c[nt2][1] + f0.y);
                float e2 = __expf(c[nt2][2] + f1.x);
                float e3 = __expf(c[nt2][3] + f1.y);
                l0 += e0 + e1; l1 += e2 + e3;
                a[nt2*2 + 0] = hpack2(e0, e1);
                a[nt2*2 + 1] = hpack2(e2, e3);
            }
            // ---- V fragments (trans) + PV: P x V ----
            uint32_t vv[4][2];
            #pragma unroll
            for (int nh = 0; nh < 2; nh++) {
                int vrow = kc*16 + (lane & 15);
                int qv = nh*2 + (lane >> 4);
                uint32_t off = vrow*64 + ((uint32_t)(qv ^ ((vrow>>1)&3)) << 4);
                uint32_t r[4];
                ldsm_x4_t(r, s0 + 4096 + off);
                vv[nh*2+0][0] = r[0]; vv[nh*2+0][1] = r[1];
                vv[nh*2+1][0] = r[2]; vv[nh*2+1][1] = r[3];
            }
            #pragma unroll
            for (int nv = 0; nv < 4; nv++)
                mma_16816h(o[nv], a, vv[nv]);
        }
        __syncthreads();
        if (jt4 + 2 < 4) ATTN_ISSUE(jbase + jt4 + 2, jt4 & 1);
    }
    #undef ATTN_ISSUE

    // reduce l across the quad sharing each row
    l0 += __shfl_xor_sync(0xffffffffu, l0, 1);
    l0 += __shfl_xor_sync(0xffffffffu, l0, 2);
    l1 += __shfl_xor_sync(0xffffffffu, l1, 1);
    l1 += __shfl_xor_sync(0xffffffffu, l1, 2);

    // store partials (no normalization here)
    const int i_r = i0 + qrow;
    const size_t pbase = ((size_t)(s*Hh + h)*Nn + i_r)*DHd;
    #pragma unroll
    for (int nv = 0; nv < 4; nv++) {
        int dh = nv*8 + (lane & 3)*2;
        *(float2*)&g_po[pbase + dh]          = make_float2(o[nv][0], o[nv][1]);
        *(float2*)&g_po[pbase + 8*DHd + dh]  = make_float2(o[nv][2], o[nv][3]);
    }
    if ((lane & 3) == 0) {
        g_pl[(size_t)(s*Hh + h)*Nn + i_r]     = l0;
        g_pl[(size_t)(s*Hh + h)*Nn + i_r + 8] = l1;
    }
}

// ---------------------------------------------------------------------------
// Kernel 2b: split-K combine over 4 partials.  out = sum(o_k)/sum(l_k).
// ---------------------------------------------------------------------------
__global__ __launch_bounds__(128) void attn_combine()
{
    const int u = blockIdx.x * 128 + threadIdx.x;   // 0 .. 131071
    const int d8 = (u & 3) * 8;
    const int i  = (u >> 2) & 1023;
    const int h  = (u >> 12) & 15;
    const int b  = u >> 16;

    float l = 0.f;
    float v[8] = {};
    #pragma unroll
    for (int k = 0; k < 4; k++) {
        const size_t r = (((size_t)((b*4 + k)*Hh + h)*Nn + i))*DHd + d8;
        l += g_pl[((size_t)(b*4 + k)*Hh + h)*Nn + i];
        float4 a0 = *(const float4*)&g_po[r];
        float4 a1 = *(const float4*)&g_po[r + 4];
        v[0] += a0.x; v[1] += a0.y; v[2] += a0.z; v[3] += a0.w;
        v[4] += a1.x; v[5] += a1.y; v[6] += a1.z; v[7] += a1.w;
    }
    const float inv = 1.0f / l;

    uint2 uh, ul;
    splith2(v[0]*inv, v[1]*inv, uh.x, ul.x);
    splith2(v[2]*inv, v[3]*inv, uh.y, ul.y);
    const size_t e = ((size_t)(b*Nn + i))*Dd + h*DHd + d8;
    *(uint2*)&g_atthi[e] = uh;
    *(uint2*)&g_attlo[e] = ul;
    splith2(v[4]*inv, v[5]*inv, uh.x, ul.x);
    splith2(v[6]*inv, v[7]*inv, uh.y, ul.y);
    *(uint2*)&g_atthi[e + 4] = uh;
    *(uint2*)&g_attlo[e + 4] = ul;
}

// ---------------------------------------------------------------------------
// Kernel 3: FF GEMM + residual + bias.
// ---------------------------------------------------------------------------
__global__ __launch_bounds__(256) void gemm_ff_mma(
    const float* __restrict__ xres, const float* __restrict__ ffb)
{
    extern __shared__ __align__(16) char smem[];
    const int m0 = blockIdx.y * 64, o0 = blockIdx.x * 128;
    float acc[2][4][4] = {};
    mma_mainloop<2>(g_atthi, g_attlo, g_fw16, m0, o0, smem, acc);

    const int tid = threadIdx.x, warp = tid >> 5, lane = tid & 31;
    const int wm = warp >> 2, wn = warp & 3;
    #pragma unroll
    for (int mf = 0; mf < 2; mf++) {
        int r0 = m0 + wm*32 + mf*16 + (lane >> 2);
        #pragma unroll
        for (int nf = 0; nf < 4; nf++) {
            int o = o0 + wn*32 + nf*8 + (lane & 3)*2;
            float2 fb = *(const float2*)&ffb[o];
            float2 x0 = *(const float2*)&xres[(size_t)r0*512 + o];
            float2 x1 = *(const float2*)&xres[(size_t)(r0+8)*512 + o];
            *(float2*)&g_y[(size_t)r0*512 + o] = make_float2(
                acc[mf][nf][0] + x0.x + fb.x, acc[mf][nf][1] + x0.y + fb.y);
            *(float2*)&g_y[(size_t)(r0+8)*512 + o] = make_float2(
                acc[mf][nf][2] + x1.x + fb.x, acc[mf][nf][3] + x1.y + fb.y);
        }
    }
}

// ---------------------------------------------------------------------------
// Kernel 4: LayerNorm rows of g_y -> out.
// ---------------------------------------------------------------------------
__global__ __launch_bounds__(128) void ln_kernel(
    const float* __restrict__ lnw, const float* __restrict__ lnb,
    float* __restrict__ out)
{
    const int row = blockIdx.x;
    const int t = threadIdx.x;
    const float4 v = ((const float4*)&g_y[(size_t)row*512])[t];

    float s  = v.x + v.y + v.z + v.w;
    float ss = v.x*v.x + v.y*v.y + v.z*v.z + v.w*v.w;

    __shared__ float rs[4], rss[4];
    #pragma unroll
    for (int off = 16; off > 0; off >>= 1) {
        s  += __shfl_down_sync(0xffffffffu, s,  off);
        ss += __shfl_down_sync(0xffffffffu, ss, off);
    }
    if ((t & 31) == 0) { rs[t >> 5] = s; rss[t >> 5] = ss; }
    __syncthreads();
    float sum  = rs[0]  + rs[1]  + rs[2]  + rs[3];
    float sums = rss[0] + rss[1] + rss[2] + rss[3];

    const float mu   = sum  * (1.0f/512.0f);
    const float var  = sums * (1.0f/512.0f) - mu*mu;
    const float rstd = rsqrtf(var + 1e-5f);

    const float4 w = ((const float4*)lnw)[t];
    const float4 b = ((const float4*)lnb)[t];
    float4 o;
    o.x = (v.x - mu)*rstd*w.x + b.x;
    o.y = (v.y - mu)*rstd*w.y + b.y;
    o.z = (v.z - mu)*rstd*w.z + b.z;
    o.w = (v.w - mu)*rstd*w.w + b.w;
    ((float4*)&out[(size_t)row*512])[t] = o;
}

// ---------------------------------------------------------------------------
extern "C" void kernel_launch(void* const* d_in, const int* in_sizes, int n_in,
                              void* d_out, int out_size)
{
    const float* x         = (const float*)d_in[0];
    const float* pdist     = (const float*)d_in[1];
    const float* angle     = (const float*)d_in[2];
    const float* adj       = (const float*)d_in[3];
    const unsigned char* mask = (const unsigned char*)d_in[4];
    const float* gamma_p   = (const float*)d_in[5];
    const float* gamma_adj = (const float*)d_in[6];
    const float* w_bias    = (const float*)d_in[7];
    const float* att_w     = (const float*)d_in[8];
    const float* ff_w      = (const float*)d_in[9];
    const float* ff_b      = (const float*)d_in[10];
    const float* ln_w      = (const float*)d_in[11];
    const float* ln_b      = (const float*)d_in[12];
    float* out = (float*)d_out;

    __half *xhi, *xlo, *w16, *fw16, *bias;
    cudaGetSymbolAddress((void**)&xhi,  g_xhi);
    cudaGetSymbolAddress((void**)&xlo,  g_xlo);
    cudaGetSymbolAddress((void**)&w16,  g_w16);
    cudaGetSymbolAddress((void**)&fw16, g_fw16);
    cudaGetSymbolAddress((void**)&bias, g_bias);

    static cudaStream_t s2 = nullptr;
    static cudaEvent_t ev_fork = nullptr, ev_join = nullptr;
    if (!s2) {
        cudaFuncSetAttribute(gemm_qkv_mma,
            cudaFuncAttributeMaxDynamicSharedMemorySize, GEMM_SMEM);
        cudaFuncSetAttribute(gemm_ff_mma,
            cudaFuncAttributeMaxDynamicSharedMemorySize, GEMM_SMEM);
        cudaStreamCreateWithFlags(&s2, cudaStreamNonBlocking);
        cudaEventCreateWithFlags(&ev_fork, cudaEventDisableTiming);
        cudaEventCreateWithFlags(&ev_join, cudaEventDisableTiming);
    }

    // Fork: bias precompute (DRAM-bound) runs concurrently with
    // split_all -> qkv GEMM (tensor-bound) on the main stream.
    cudaEventRecord(ev_fork, 0);
    cudaStreamWaitEvent(s2, ev_fork, 0);
    bias_kernel<<<(Bsz*Nn*Nn/4)/256, 256, 0, s2>>>(pdist, angle, adj, mask,
                                                   gamma_p, gamma_adj, w_bias);
    cudaEventRecord(ev_join, s2);

    split_all<<<(SPLIT_TOT + 255)/256, 256>>>(x, att_w, ff_w, xhi, xlo, w16, fw16);
    gemm_qkv_mma<<<dim3(1536/128, 2048/64), 256, GEMM_SMEM>>>();

    // Join: attention needs both qkv outputs and the bias tensor.
    cudaStreamWaitEvent(0, ev_join, 0);
    attn_mma<<<dim3(Nn/64, Hh, Bsz*4), 128>>>(bias);
    attn_combine<<<1024, 128>>>();
    gemm_ff_mma<<<dim3(512/128, 2048/64), 256, GEMM_SMEM>>>(x, ff_b);
    ln_kernel<<<Bsz*Nn, 128>>>(ln_w, ln_b, out);
}

// round 17
// speedup vs baseline: 1.0311x; 1.0311x over previous
#include <cuda_runtime.h>
#include <cuda_bf16.h>
#include <cuda_fp16.h>
#include <math.h>
#include <stdint.h>

#define Bsz 2
#define Nn  1024
#define Dd  512
#define Hh  16
#define DHd 32

// Scratch (device globals; no allocation allowed)
__device__ float g_y[Bsz*Nn*Dd];         // pre-LN residual

// fp16 operands
__device__ __half g_xhi[Bsz*Nn*Dd],  g_xlo[Bsz*Nn*Dd];   // x hi/lo
__device__ __half g_w16[1536*Dd];                         // att_w single
__device__ __half g_fw16[Dd*Dd];                          // ff_w single
__device__ __half g_atthi[Bsz*Nn*Dd], g_attlo[Bsz*Nn*Dd]; // attn out hi/lo
// Attention operands: Q hi/lo (pre-scaled), K single, V single
__device__ __half g_qh16[Bsz*Hh*Nn*DHd], g_ql16[Bsz*Hh*Nn*DHd];
__device__ __half g_k16 [Bsz*Hh*Nn*DHd];
__device__ __half g_v16 [Bsz*Hh*Nn*DHd];
// fused additive bias, fp16, [B,H,N,N] (masked entries = -60000)
__device__ __half g_bias[(size_t)Bsz*Hh*Nn*Nn];
// split-K partials: [B*2 splits][H][N][32] fp32 + row sums
__device__ float g_po[(size_t)Bsz*2*Hh*Nn*DHd];
__device__ float g_pl[(size_t)Bsz*2*Hh*Nn];

// ===================== warp-MMA helpers ====================================
__device__ __forceinline__ uint32_t smem_u32(const void* p) {
    uint32_t a;
    asm("{ .reg .u64 t; cvta.to.shared.u64 t, %1; cvt.u32.u64 %0, t; }"
        : "=r"(a) : "l"(p));
    return a;
}
__device__ __forceinline__ void ldsm_x4(uint32_t* r, uint32_t addr) {
    asm volatile("ldmatrix.sync.aligned.m8n8.x4.shared.b16 {%0,%1,%2,%3}, [%4];"
        : "=r"(r[0]), "=r"(r[1]), "=r"(r[2]), "=r"(r[3]) : "r"(addr));
}
__device__ __forceinline__ void ldsm_x4_t(uint32_t* r, uint32_t addr) {
    asm volatile("ldmatrix.sync.aligned.m8n8.x4.trans.shared.b16 {%0,%1,%2,%3}, [%4];"
        : "=r"(r[0]), "=r"(r[1]), "=r"(r[2]), "=r"(r[3]) : "r"(addr));
}
__device__ __forceinline__ void mma_16816h(float* c, const uint32_t* a, const uint32_t* b) {
    asm volatile("mma.sync.aligned.m16n8k16.row.col.f32.f16.f16.f32 "
        "{%0,%1,%2,%3}, {%4,%5,%6,%7}, {%8,%9}, {%0,%1,%2,%3};"
        : "+f"(c[0]), "+f"(c[1]), "+f"(c[2]), "+f"(c[3])
        : "r"(a[0]), "r"(a[1]), "r"(a[2]), "r"(a[3]), "r"(b[0]), "r"(b[1]));
}
__device__ __forceinline__ void cp_async16(uint32_t saddr, const void* gaddr) {
    asm volatile("cp.async.cg.shared.global [%0], [%1], 16;"
                 :: "r"(saddr), "l"(gaddr) : "memory");
}
__device__ __forceinline__ uint32_t hpack2(float x0, float x1) {
    __half2 h = __floats2half2_rn(x0, x1);
    return *(uint32_t*)&h;
}
__device__ __forceinline__ void splith2(float x0, float x1, uint32_t& uh, uint32_t& ul) {
    __half h0 = __float2half_rn(x0), h1 = __float2half_rn(x1);
    __half l0 = __float2half_rn(x0 - __half2float(h0));
    __half l1 = __float2half_rn(x1 - __half2float(h1));
    uh = (uint32_t)__half_as_ushort(h0) | ((uint32_t)__half_as_ushort(h1) << 16);
    ul = (uint32_t)__half_as_ushort(l0) | ((uint32_t)__half_as_ushort(l1) << 16);
}

// ---------------------------------------------------------------------------
// Kernel 0: preprocessing — x -> fp16 hi/lo; att_w, ff_w -> fp16 single.
// ---------------------------------------------------------------------------
#define SPLIT_N1 (Bsz*Nn*Dd/4)
#define SPLIT_N2 (1536*Dd/4)
#define SPLIT_N3 (Dd*Dd/4)
#define SPLIT_TOT (SPLIT_N1 + SPLIT_N2 + SPLIT_N3)

__global__ __launch_bounds__(256) void split_all(
    const float* __restrict__ x, const float* __restrict__ w,
    const float* __restrict__ fw,
    __half* __restrict__ xhi, __half* __restrict__ xlo,
    __half* __restrict__ w16, __half* __restrict__ fw16)
{
    int idx = blockIdx.x * 256 + threadIdx.x;
    if (idx < SPLIT_N1) {
        float4 v = ((const float4*)x)[idx];
        uint2 uh, ul;
        splith2(v.x, v.y, uh.x, ul.x);
        splith2(v.z, v.w, uh.y, ul.y);
        *(uint2*)&xhi[(size_t)idx*4] = uh;
        *(uint2*)&xlo[(size_t)idx*4] = ul;
    } else if (idx < SPLIT_N1 + SPLIT_N2) {
        int i = idx - SPLIT_N1;
        float4 v = ((const float4*)w)[i];
        uint2 pk;
        pk.x = hpack2(v.x, v.y);
        pk.y = hpack2(v.z, v.w);
        *(uint2*)&w16[(size_t)i*4] = pk;
    } else if (idx < SPLIT_TOT) {
        int i = idx - SPLIT_N1 - SPLIT_N2;
        float4 v = ((const float4*)fw)[i];
        uint2 pk;
        pk.x = hpack2(v.x, v.y);
        pk.y = hpack2(v.z, v.w);
        *(uint2*)&fw16[(size_t)i*4] = pk;
    }
}

// ---------------------------------------------------------------------------
// Kernel 0b: fused bias precompute (fp16; masked -> -60000).
// ---------------------------------------------------------------------------
__global__ __launch_bounds__(256) void bias_kernel(
    const float* __restrict__ pdist, const float* __restrict__ angle,
    const float* __restrict__ adj,   const unsigned char* __restrict__ mask,
    const float* __restrict__ gamma_p, const float* __restrict__ gamma_adj,
    const float* __restrict__ w_bias)
{
    const int idx = blockIdx.x * 256 + threadIdx.x;
    const int jc = idx & 255;
    const int bi = idx >> 8;
    const int b = bi >> 10;
    const int ii = bi & 1023;
    const int j = jc * 4;
    const size_t base = (size_t)bi * Nn + j;

    const float4 pd  = *(const float4*)&pdist[base];
    const float4 aj  = *(const float4*)&adj[base];
    const float4 an0 = *(const float4*)&angle[2*base];
    const float4 an1 = *(const float4*)&angle[2*base + 4];
    const unsigned char* mk = mask + b*Nn + j;
    const bool m0 = mk[0], m1 = mk[1], m2 = mk[2], m3 = mk[3];

    #pragma unroll
    for (int h = 0; h < Hh; h++) {
        const float gp = gamma_p[h], ga = gamma_adj[h];
        const float w0 = w_bias[2*h], w1 = w_bias[2*h+1];
        float s0 = -gp*pd.x + w0*an0.x + w1*an0.y + ga*aj.x;
        float s1 = -gp*pd.y + w0*an0.z + w1*an0.w + ga*aj.y;
        float s2 = -gp*pd.z + w0*an1.x + w1*an1.y + ga*aj.z;
        float s3 = -gp*pd.w + w0*an1.z + w1*an1.w + ga*aj.w;
        if (m0) s0 = -60000.f;
        if (m1) s1 = -60000.f;
        if (m2) s2 = -60000.f;
        if (m3) s3 = -60000.f;
        uint2 pk;
        pk.x = hpack2(s0, s1);
        pk.y = hpack2(s2, s3);
        const size_t off = (((size_t)(b*Hh + h)*Nn + ii)*Nn + j);
        *(uint2*)&g_bias[off] = pk;
    }
}

// ---------------------------------------------------------------------------
// cp.async double-buffered fp16 MMA mainloop (proven R13/R14).
// ---------------------------------------------------------------------------
template<int MFR>
__device__ __forceinline__ void mma_mainloop(
    const __half* __restrict__ gAhi, const __half* __restrict__ gAlo,
    const __half* __restrict__ gB,
    int m0, int o0, char* smem, float (&acc)[MFR][4][4])
{
    constexpr int MT = MFR * 32;
    constexpr int S_ALO = MT * 64;
    constexpr int S_B   = 2 * MT * 64;
    constexpr int STAGE = 2 * MT * 64 + 8192;
    const int tid = threadIdx.x;
    const int warp = tid >> 5, lane = tid & 31;
    const int wm = warp >> 2, wn = warp & 3;
    const uint32_t sb = smem_u32(smem);

    #define ISSUE_CHUNK(kc, st) do { \
        uint32_t s0 = sb + (st) * STAGE; \
        _Pragma("unroll") \
        for (int i = 0; i < MFR/2; i++) { \
            int u = tid + i*256; \
            int row = u >> 2, q = u & 3; \
            uint32_t off = row*64 + ((uint32_t)(q ^ ((row>>1)&3)) << 4); \
            size_t g = (size_t)(m0 + row)*512 + (kc)*32 + q*8; \
            cp_async16(s0 + off,         &gAhi[g]); \
            cp_async16(s0 + S_ALO + off, &gAlo[g]); \
        } \
        _Pragma("unroll") \
        for (int i = 0; i < 2; i++) { \
            int u = tid + i*256; \
            int row = u >> 2, q = u & 3; \
            uint32_t off = row*64 + ((uint32_t)(q ^ ((row>>1)&3)) << 4); \
            size_t g = (size_t)(o0 + row)*512 + (kc)*32 + q*8; \
            cp_async16(s0 + S_B + off, &gB[g]); \
        } \
        asm volatile("cp.async.commit_group;" ::: "memory"); \
    } while (0)

    ISSUE_CHUNK(0, 0);
    ISSUE_CHUNK(1, 1);

    for (int kc = 0; kc < 16; kc++) {
        if (kc < 15) asm volatile("cp.async.wait_group 1;" ::: "memory");
        else         asm volatile("cp.async.wait_group 0;" ::: "memory");
        __syncthreads();
        const uint32_t s0 = sb + (uint32_t)(kc & 1) * STAGE;
        #pragma unroll
        for (int ks = 0; ks < 2; ks++) {
            uint32_t bh[4][2];
            #pragma unroll
            for (int p = 0; p < 2; p++) {
                int nrow = wn*32 + p*16 + (lane & 7) + ((lane >> 4) << 3);
                int qb = ks*2 + ((lane >> 3) & 1);
                uint32_t off = nrow*64 + ((uint32_t)(qb ^ ((nrow>>1)&3)) << 4);
                uint32_t r[4];
                ldsm_x4(r, s0 + S_B + off);
                bh[2*p][0] = r[0]; bh[2*p][1] = r[1];
                bh[2*p+1][0] = r[2]; bh[2*p+1][1] = r[3];
            }
            #pragma unroll
            for (int mf = 0; mf < MFR; mf++) {
                int arow = wm*(MFR*16) + mf*16 + (lane & 15);
                int qb = ks*2 + (lane >> 4);
                uint32_t off = arow*64 + ((uint32_t)(qb ^ ((arow>>1)&3)) << 4);
                uint32_t ah[4], al[4];
                ldsm_x4(ah, s0 + off);
                ldsm_x4(al, s0 + S_ALO + off);
                #pragma unroll
                for (int nf = 0; nf < 4; nf++) {
                    mma_16816h(acc[mf][nf], ah, bh[nf]);
                    mma_16816h(acc[mf][nf], al, bh[nf]);
                }
            }
        }
        __syncthreads();
        if (kc + 2 < 16) ISSUE_CHUNK(kc + 2, kc & 1);
    }
    #undef ISSUE_CHUNK
}

#define GEMM_SMEM (2 * (2*64*64 + 8192))   // MFR=2: 32768 bytes (2 stages)

// ---------------------------------------------------------------------------
// Kernel 1: QKV GEMM. CTA 64x128, grid (12, 32). Epilogue writes fp16:
// Q hi/lo (pre-scaled), K single, V single, all [B,H,N,32].
// ---------------------------------------------------------------------------
__global__ __launch_bounds__(256) void gemm_qkv_mma()
{
    extern __shared__ __align__(16) char smem[];
    const int m0 = blockIdx.y * 64, o0 = blockIdx.x * 128;
    float acc[2][4][4] = {};
    mma_mainloop<2>(g_xhi, g_xlo, g_w16, m0, o0, smem, acc);

    const float SCALE = 0.17677669529663689f;  // 1/sqrt(32)
    const int tid = threadIdx.x, warp = tid >> 5, lane = tid & 31;
    const int wm = warp >> 2, wn = warp & 3;
    const int bb = m0 >> 10;
    #pragma unroll
    for (int mf = 0; mf < 2; mf++) {
        int r0 = (m0 & 1023) + wm*32 + mf*16 + (lane >> 2);
        #pragma unroll
        for (int nf = 0; nf < 4; nf++) {
            int o = o0 + wn*32 + nf*8 + (lane & 3)*2;
            int which = o >> 9, h = (o >> 5) & 15, d = o & 31;
            size_t e0 = ((size_t)(bb*Hh + h)*Nn + r0)*DHd + d;
            size_t e1 = e0 + 8*DHd;
            if (which == 0) {
                uint32_t uh, ul;
                splith2(acc[mf][nf][0]*SCALE, acc[mf][nf][1]*SCALE, uh, ul);
                *(uint32_t*)&g_qh16[e0] = uh; *(uint32_t*)&g_ql16[e0] = ul;
                splith2(acc[mf][nf][2]*SCALE, acc[mf][nf][3]*SCALE, uh, ul);
                *(uint32_t*)&g_qh16[e1] = uh; *(uint32_t*)&g_ql16[e1] = ul;
            } else if (which == 1) {
                *(uint32_t*)&g_k16[e0] = hpack2(acc[mf][nf][0], acc[mf][nf][1]);
                *(uint32_t*)&g_k16[e1] = hpack2(acc[mf][nf][2], acc[mf][nf][3]);
            } else {
                *(uint32_t*)&g_v16[e0] = hpack2(acc[mf][nf][0], acc[mf][nf][1]);
                *(uint32_t*)&g_v16[e1] = hpack2(acc[mf][nf][2], acc[mf][nf][3]);
            }
        }
    }
}

// ---------------------------------------------------------------------------
// Kernel 2: Split-K (2-way) tensor-core attention. Bias initializes the QK
// accumulator (removes the bias FADDs). Exact decomposition; combine adds.
// Grid (16 qtiles, 16 heads, B*2). Block 128 thr (4 warps x 16 queries).
// Per stage SMEM: K(4096) | V(4096) | bias(9216, 144B rows, conflict-free).
// ---------------------------------------------------------------------------
#define ASTAGE 17408   // 4096 + 4096 + 9216

__global__ __launch_bounds__(128) void attn_mma(const __half* __restrict__ gbias)
{
    __shared__ __align__(16) char sQh[4096];
    __shared__ __align__(16) char sQl[4096];
    __shared__ __align__(16) char sKV[2][ASTAGE];

    const int s = blockIdx.z;            // b*2 + split
    const int b = s >> 1, split = s & 1;
    const int h = blockIdx.y;
    const int i0 = blockIdx.x * 64;
    const int t = threadIdx.x, w = t >> 5, lane = t & 31;
    const int jbase = split * 8;         // first key tile of this split

    const size_t ho = (size_t)(b*Hh + h)*Nn*DHd;
    const __half* gQh = g_qh16 + ho;
    const __half* gQl = g_ql16 + ho;
    const __half* gK  = g_k16  + ho;
    const __half* gV  = g_v16  + ho;
    const __half* gB  = gbias + ((size_t)(b*Hh + h)*Nn + i0)*Nn;  // [64][N]

    const uint32_t sbQh = smem_u32(sQh), sbQl = smem_u32(sQl);
    const uint32_t sbKV = smem_u32(sKV);

    #define ATTN_ISSUE(jt, st) do { \
        const int _j0 = (jt)*64; \
        uint32_t s0 = sbKV + (uint32_t)(st)*ASTAGE; \
        _Pragma("unroll") \
        for (int u0 = 0; u0 < 2; u0++) { \
            int u = t + u0*128; \
            int row = u >> 2, q = u & 3; \
            uint32_t off = row*64 + ((uint32_t)(q ^ ((row>>1)&3)) << 4); \
            size_t g = (size_t)(_j0 + row)*DHd + q*8; \
            cp_async16(s0 + off,        &gK[g]); \
            cp_async16(s0 + 4096 + off, &gV[g]); \
        } \
        _Pragma("unroll") \
        for (int u0 = 0; u0 < 4; u0++) { \
            int u = t + u0*128; \
            int row = u >> 3, q = u & 7; \
            cp_async16(s0 + 8192 + row*144 + q*16, \
                       &gB[(size_t)row*Nn + _j0 + q*8]); \
        } \
        asm volatile("cp.async.commit_group;" ::: "memory"); \
    } while (0)

    // Stage Q tile; kick off first two K/V/bias tiles of this split
    #pragma unroll
    for (int u0 = 0; u0 < 2; u0++) {
        int u = t + u0*128;
        int row = u >> 2, q = u & 3;
        uint32_t off = row*64 + ((uint32_t)(q ^ ((row>>1)&3)) << 4);
        size_t g = (size_t)(i0 + row)*DHd + q*8;
        *(uint4*)(sQh + off) = *(const uint4*)&gQh[g];
        *(uint4*)(sQl + off) = *(const uint4*)&gQl[g];
    }
    ATTN_ISSUE(jbase + 0, 0);
    ATTN_ISSUE(jbase + 1, 1);
    __syncthreads();

    uint32_t qh[2][4], ql[2][4];
    #pragma unroll
    for (int ks = 0; ks < 2; ks++) {
        int arow = w*16 + (lane & 15);
        int qb = ks*2 + (lane >> 4);
        uint32_t off = arow*64 + ((uint32_t)(qb ^ ((arow>>1)&3)) << 4);
        ldsm_x4(qh[ks], sbQh + off);
        ldsm_x4(ql[ks], sbQl + off);
    }

    const int qrow = w*16 + (lane >> 2);
    const uint32_t brow0 = 8192 + qrow*144;
    const uint32_t brow1 = 8192 + (qrow + 8)*144;

    float o[4][4] = {};
    float l0 = 0.f, l1 = 0.f;

    for (int jt8 = 0; jt8 < 8; jt8++) {
        if (jt8 < 7) asm volatile("cp.async.wait_group 1;" ::: "memory");
        else         asm volatile("cp.async.wait_group 0;" ::: "memory");
        __syncthreads();
        const uint32_t s0 = sbKV + (uint32_t)(jt8 & 1)*ASTAGE;
        const char* sbias = (const char*)sKV[jt8 & 1];

        #pragma unroll
        for (int kc = 0; kc < 4; kc++) {
            // ---- K fragments (single fp16) ----
            uint32_t kk[2][2][2];
            #pragma unroll
            for (int ks = 0; ks < 2; ks++) {
                int nrow = kc*16 + (lane & 7) + ((lane >> 4) << 3);
                int qb = ks*2 + ((lane >> 3) & 1);
                uint32_t off = nrow*64 + ((uint32_t)(qb ^ ((nrow>>1)&3)) << 4);
                uint32_t r[4];
                ldsm_x4(r, s0 + off);
                kk[ks][0][0] = r[0]; kk[ks][0][1] = r[1];
                kk[ks][1][0] = r[2]; kk[ks][1][1] = r[3];
            }
            // ---- init accumulators with bias (from SMEM), then QK MMAs ----
            float c[2][4];
            #pragma unroll
            for (int nt2 = 0; nt2 < 2; nt2++) {
                int jb = ((kc*2 + nt2)*8 + (lane & 3)*2) * 2;
                float2 f0 = __half22float2(*(const __half2*)(sbias + brow0 + jb));
                float2 f1 = __half22float2(*(const __half2*)(sbias + brow1 + jb));
                c[nt2][0] = f0.x; c[nt2][1] = f0.y;
                c[nt2][2] = f1.x; c[nt2][3] = f1.y;
            }
            #pragma unroll
            for (int nt2 = 0; nt2 < 2; nt2++)
                #pragma unroll
                for (int ks = 0; ks < 2; ks++) {
                    mma_16816h(c[nt2], qh[ks], kk[ks][nt2]);
                    mma_16816h(c[nt2], ql[ks], kk[ks][nt2]);
                }
            // ---- exp + pack P as fp16 ----
            uint32_t a[4];
            #pragma unroll
            for (int nt2 = 0; nt2 < 2; nt2++) {
                float e0 = __expf(c[nt2][0]);
                float e1 = __expf(c[nt2][1]);
                float e2 = __expf(c[nt2][2]);
                float e3 = __expf(c[nt2][3]);
                l0 += e0 + e1; l1 += e2 + e3;
                a[nt2*2 + 0] = hpack2(e0, e1);
                a[nt2*2 + 1] = hpack2(e2, e3);
            }
            // ---- V fragments (trans) + PV: P x V ----
            uint32_t vv[4][2];
            #pragma unroll
            for (int nh = 0; nh < 2; nh++) {
                int vrow = kc*16 + (lane & 15);
                int qv = nh*2 + (lane >> 4);
                uint32_t off = vrow*64 + ((uint32_t)(qv ^ ((vrow>>1)&3)) << 4);
                uint32_t r[4];
                ldsm_x4_t(r, s0 + 4096 + off);
                vv[nh*2+0][0] = r[0]; vv[nh*2+0][1] = r[1];
                vv[nh*2+1][0] = r[2]; vv[nh*2+1][1] = r[3];
            }
            #pragma unroll
            for (int nv = 0; nv < 4; nv++)
                mma_16816h(o[nv], a, vv[nv]);
        }
        __syncthreads();
        if (jt8 + 2 < 8) ATTN_ISSUE(jbase + jt8 + 2, jt8 & 1);
    }
    #undef ATTN_ISSUE

    // reduce l across the quad sharing each row
    l0 += __shfl_xor_sync(0xffffffffu, l0, 1);
    l0 += __shfl_xor_sync(0xffffffffu, l0, 2);
    l1 += __shfl_xor_sync(0xffffffffu, l1, 1);
    l1 += __shfl_xor_sync(0xffffffffu, l1, 2);

    // store partials (no normalization here)
    const int i_r = i0 + qrow;
    const size_t pbase = ((size_t)(s*Hh + h)*Nn + i_r)*DHd;
    #pragma unroll
    for (int nv = 0; nv < 4; nv++) {
        int dh = nv*8 + (lane & 3)*2;
        *(float2*)&g_po[pbase + dh]          = make_float2(o[nv][0], o[nv][1]);
        *(float2*)&g_po[pbase + 8*DHd + dh]  = make_float2(o[nv][2], o[nv][3]);
    }
    if ((lane & 3) == 0) {
        g_pl[(size_t)(s*Hh + h)*Nn + i_r]     = l0;
        g_pl[(size_t)(s*Hh + h)*Nn + i_r + 8] = l1;
    }
}

// ---------------------------------------------------------------------------
// Kernel 2b: split-K combine (2 partials).  out = (o0+o1)/(l0+l1), fp16 hi/lo.
// ---------------------------------------------------------------------------
__global__ __launch_bounds__(128) void attn_combine()
{
    const int u = blockIdx.x * 128 + threadIdx.x;   // 0 .. 131071
    const int d8 = (u & 3) * 8;
    const int i  = (u >> 2) & 1023;
    const int h  = (u >> 12) & 15;
    const int b  = u >> 16;

    const size_t r0 = (((size_t)((b*2 + 0)*Hh + h)*Nn + i))*DHd + d8;
    const size_t r1 = (((size_t)((b*2 + 1)*Hh + h)*Nn + i))*DHd + d8;
    const float l = g_pl[((size_t)(b*2 + 0)*Hh + h)*Nn + i]
                  + g_pl[((size_t)(b*2 + 1)*Hh + h)*Nn + i];
    const float inv = 1.0f / l;

    float4 a0 = *(const float4*)&g_po[r0];
    float4 a1 = *(const float4*)&g_po[r0 + 4];
    float4 b0 = *(const float4*)&g_po[r1];
    float4 b1 = *(const float4*)&g_po[r1 + 4];

    float v0 = (a0.x + b0.x)*inv, v1 = (a0.y + b0.y)*inv;
    float v2 = (a0.z + b0.z)*inv, v3 = (a0.w + b0.w)*inv;
    float v4 = (a1.x + b1.x)*inv, v5 = (a1.y + b1.y)*inv;
    float v6 = (a1.z + b1.z)*inv, v7 = (a1.w + b1.w)*inv;

    uint2 uh, ul;
    splith2(v0, v1, uh.x, ul.x);
    splith2(v2, v3, uh.y, ul.y);
    const size_t e = ((size_t)(b*Nn + i))*Dd + h*DHd + d8;
    *(uint2*)&g_atthi[e] = uh;
    *(uint2*)&g_attlo[e] = ul;
    splith2(v4, v5, uh.x, ul.x);
    splith2(v6, v7, uh.y, ul.y);
    *(uint2*)&g_atthi[e + 4] = uh;
    *(uint2*)&g_attlo[e + 4] = ul;
}

// ---------------------------------------------------------------------------
// Kernel 3: FF GEMM + residual + bias.
// ---------------------------------------------------------------------------
__global__ __launch_bounds__(256) void gemm_ff_mma(
    const float* __restrict__ xres, const float* __restrict__ ffb)
{
    extern __shared__ __align__(16) char smem[];
    const int m0 = blockIdx.y * 64, o0 = blockIdx.x * 128;
    float acc[2][4][4] = {};
    mma_mainloop<2>(g_atthi, g_attlo, g_fw16, m0, o0, smem, acc);

    const int tid = threadIdx.x, warp = tid >> 5, lane = tid & 31;
    const int wm = warp >> 2, wn = warp & 3;
    #pragma unroll
    for (int mf = 0; mf < 2; mf++) {
        int r0 = m0 + wm*32 + mf*16 + (lane >> 2);
        #pragma unroll
        for (int nf = 0; nf < 4; nf++) {
            int o = o0 + wn*32 + nf*8 + (lane & 3)*2;
            float2 fb = *(const float2*)&ffb[o];
            float2 x0 = *(const float2*)&xres[(size_t)r0*512 + o];
            float2 x1 = *(const float2*)&xres[(size_t)(r0+8)*512 + o];
            *(float2*)&g_y[(size_t)r0*512 + o] = make_float2(
                acc[mf][nf][0] + x0.x + fb.x, acc[mf][nf][1] + x0.y + fb.y);
            *(float2*)&g_y[(size_t)(r0+8)*512 + o] = make_float2(
                acc[mf][nf][2] + x1.x + fb.x, acc[mf][nf][3] + x1.y + fb.y);
        }
    }
}

// ---------------------------------------------------------------------------
// Kernel 4: LayerNorm rows of g_y -> out.
// ---------------------------------------------------------------------------
__global__ __launch_bounds__(128) void ln_kernel(
    const float* __restrict__ lnw, const float* __restrict__ lnb,
    float* __restrict__ out)
{
    const int row = blockIdx.x;
    const int t = threadIdx.x;
    const float4 v = ((const float4*)&g_y[(size_t)row*512])[t];

    float s  = v.x + v.y + v.z + v.w;
    float ss = v.x*v.x + v.y*v.y + v.z*v.z + v.w*v.w;

    __shared__ float rs[4], rss[4];
    #pragma unroll
    for (int off = 16; off > 0; off >>= 1) {
        s  += __shfl_down_sync(0xffffffffu, s,  off);
        ss += __shfl_down_sync(0xffffffffu, ss, off);
    }
    if ((t & 31) == 0) { rs[t >> 5] = s; rss[t >> 5] = ss; }
    __syncthreads();
    float sum  = rs[0]  + rs[1]  + rs[2]  + rs[3];
    float sums = rss[0] + rss[1] + rss[2] + rss[3];

    const float mu   = sum  * (1.0f/512.0f);
    const float var  = sums * (1.0f/512.0f) - mu*mu;
    const float rstd = rsqrtf(var + 1e-5f);

    const float4 w = ((const float4*)lnw)[t];
    const float4 b = ((const float4*)lnb)[t];
    float4 o;
    o.x = (v.x - mu)*rstd*w.x + b.x;
    o.y = (v.y - mu)*rstd*w.y + b.y;
    o.z = (v.z - mu)*rstd*w.z + b.z;
    o.w = (v.w - mu)*rstd*w.w + b.w;
    ((float4*)&out[(size_t)row*512])[t] = o;
}

// ---------------------------------------------------------------------------
extern "C" void kernel_launch(void* const* d_in, const int* in_sizes, int n_in,
                              void* d_out, int out_size)
{
    const float* x         = (const float*)d_in[0];
    const float* pdist     = (const float*)d_in[1];
    const float* angle     = (const float*)d_in[2];
    const float* adj       = (const float*)d_in[3];
    const unsigned char* mask = (const unsigned char*)d_in[4];
    const float* gamma_p   = (const float*)d_in[5];
    const float* gamma_adj = (const float*)d_in[6];
    const float* w_bias    = (const float*)d_in[7];
    const float* att_w     = (const float*)d_in[8];
    const float* ff_w      = (const float*)d_in[9];
    const float* ff_b      = (const float*)d_in[10];
    const float* ln_w      = (const float*)d_in[11];
    const float* ln_b      = (const float*)d_in[12];
    float* out = (float*)d_out;

    __half *xhi, *xlo, *w16, *fw16, *bias;
    cudaGetSymbolAddress((void**)&xhi,  g_xhi);
    cudaGetSymbolAddress((void**)&xlo,  g_xlo);
    cudaGetSymbolAddress((void**)&w16,  g_w16);
    cudaGetSymbolAddress((void**)&fw16, g_fw16);
    cudaGetSymbolAddress((void**)&bias, g_bias);

    static cudaStream_t s2 = nullptr;
    static cudaEvent_t ev_fork = nullptr, ev_join = nullptr;
    if (!s2) {
        cudaFuncSetAttribute(gemm_qkv_mma,
            cudaFuncAttributeMaxDynamicSharedMemorySize, GEMM_SMEM);
        cudaFuncSetAttribute(gemm_ff_mma,
            cudaFuncAttributeMaxDynamicSharedMemorySize, GEMM_SMEM);
        cudaStreamCreateWithFlags(&s2, cudaStreamNonBlocking);
        cudaEventCreateWithFlags(&ev_fork, cudaEventDisableTiming);
        cudaEventCreateWithFlags(&ev_join, cudaEventDisableTiming);
    }

    // Fork: bias precompute (DRAM-bound) concurrent with split+qkv (tensor).
    cudaEventRecord(ev_fork, 0);
    cudaStreamWaitEvent(s2, ev_fork, 0);
    bias_kernel<<<(Bsz*Nn*Nn/4)/256, 256, 0, s2>>>(pdist, angle, adj, mask,
                                                   gamma_p, gamma_adj, w_bias);
    cudaEventRecord(ev_join, s2);

    split_all<<<(SPLIT_TOT + 255)/256, 256>>>(x, att_w, ff_w, xhi, xlo, w16, fw16);
    gemm_qkv_mma<<<dim3(1536/128, 2048/64), 256, GEMM_SMEM>>>();

    // Join: attention needs both qkv outputs and the bias tensor.
    cudaStreamWaitEvent(0, ev_join, 0);
    attn_mma<<<dim3(Nn/64, Hh, Bsz*2), 128>>>(bias);
    attn_combine<<<1024, 128>>>();
    gemm_ff_mma<<<dim3(512/128, 2048/64), 256, GEMM_SMEM>>>(x, ff_b);
    ln_kernel<<<Bsz*Nn, 128>>>(ln_w, ln_b, out);
}